// round 1
// baseline (speedup 1.0000x reference)
#include <cuda_runtime.h>

#define SPATIAL 131072   // D*H*W per (batch, channel)
#define HW2     16384    // H*W
#define CCH     64

// Scratch (no allocations allowed anywhere)
__device__ float g_h [2 * CCH * SPATIAL];
__device__ float g_uv[2 * CCH * SPATIAL];

__device__ __forceinline__ unsigned long long pack_dup(float x) {
    unsigned long long u;
    asm("mov.b64 %0, {%1, %2};" : "=l"(u) : "f"(x), "f"(x));
    return u;
}
__device__ __forceinline__ void fma2(unsigned long long& d,
                                     unsigned long long a,
                                     unsigned long long b) {
    asm("fma.rn.f32x2 %0, %1, %2, %0;" : "+l"(d) : "l"(a), "l"(b));
}

// ---------------------------------------------------------------------------
// C[b][m][p] = sum_k A[m][k] * X[b][k][p]      (M=K=64, N=SPATIAL per batch)
// CTA: 64 rows x 128 cols. smem = 16KB (A^T) + 32KB (B) = 48KB exactly.
// Thread: 8 rows x 4 cols as packed f32x2 FMAs.
// ---------------------------------------------------------------------------
__device__ __forceinline__ void gemm64_body(const float* __restrict__ X,
                                            const float* __restrict__ A,
                                            float* __restrict__ C) {
    __shared__ float As[64 * 64];    // As[k*64 + m] = A[m][k]
    __shared__ float Bs[64 * 128];   // Bs[k*128 + c]
    const int t  = threadIdx.x;
    const int b  = blockIdx.y;
    const int p0 = blockIdx.x * 128;
    const float* Xb = X + b * (CCH * SPATIAL);

#pragma unroll
    for (int i = 0; i < 4; ++i) {                 // load A transposed
        int fl = t + 256 * i;                     // 0..1023 float4s->floats
        int m = fl >> 4, kq = fl & 15;
        float4 v = *reinterpret_cast<const float4*>(A + m * 64 + kq * 4);
        As[(kq * 4 + 0) * 64 + m] = v.x;
        As[(kq * 4 + 1) * 64 + m] = v.y;
        As[(kq * 4 + 2) * 64 + m] = v.z;
        As[(kq * 4 + 3) * 64 + m] = v.w;
    }
#pragma unroll
    for (int i = 0; i < 8; ++i) {                 // load B tile (64 x 128)
        int fl = t + 256 * i;                     // 0..2047 float4s
        int k = fl >> 5, cq = fl & 31;
        float4 v = *reinterpret_cast<const float4*>(Xb + k * SPATIAL + p0 + cq * 4);
        *reinterpret_cast<float4*>(&Bs[k * 128 + cq * 4]) = v;
    }
    __syncthreads();

    const int cg = t & 31;        // column group (lane)
    const int rg = t >> 5;        // row group (warp): rows rg*8..rg*8+7
    unsigned long long acc[16];
#pragma unroll
    for (int i = 0; i < 16; ++i) acc[i] = 0ull;

#pragma unroll 8
    for (int k = 0; k < 64; ++k) {
        float4 a0 = *reinterpret_cast<const float4*>(&As[k * 64 + rg * 8]);
        float4 a1 = *reinterpret_cast<const float4*>(&As[k * 64 + rg * 8 + 4]);
        float4 bv = *reinterpret_cast<const float4*>(&Bs[k * 128 + cg * 4]);
        unsigned long long b01 = reinterpret_cast<const unsigned long long*>(&bv)[0];
        unsigned long long b23 = reinterpret_cast<const unsigned long long*>(&bv)[1];
        float am[8] = {a0.x, a0.y, a0.z, a0.w, a1.x, a1.y, a1.z, a1.w};
#pragma unroll
        for (int j = 0; j < 8; ++j) {
            unsigned long long aj = pack_dup(am[j]);
            fma2(acc[2 * j],     aj, b01);
            fma2(acc[2 * j + 1], aj, b23);
        }
    }

    float* Cb = C + b * (CCH * SPATIAL);
#pragma unroll
    for (int j = 0; j < 8; ++j) {
        float2 lo = *reinterpret_cast<float2*>(&acc[2 * j]);
        float2 hi = *reinterpret_cast<float2*>(&acc[2 * j + 1]);
        float4 v = make_float4(lo.x, lo.y, hi.x, hi.y);
        *reinterpret_cast<float4*>(Cb + (rg * 8 + j) * SPATIAL + p0 + cg * 4) = v;
    }
}

__global__ void __launch_bounds__(256) gemm_head(const float* __restrict__ X,
                                                 const float* __restrict__ A) {
    gemm64_body(X, A, g_h);
}
__global__ void __launch_bounds__(256) gemm_tail(const float* __restrict__ A,
                                                 float* __restrict__ C) {
    gemm64_body(g_uv, A, C);
}

// ---------------------------------------------------------------------------
// Fused: replicate-pad + depthwise 3x3x3 (shared kernel, 3 ranks) + L2 norm
// over ranks + Vp (channel reduction) + UV contraction.
// CTA = 64 channels x 16 w positions at fixed (b, d, hh).
// ---------------------------------------------------------------------------
__global__ void __launch_bounds__(256) midkernel(const float* __restrict__ Uw,
                                                 const float* __restrict__ Vw) {
    __shared__ float hs[64 * 164];       // [c][9*18] padded stride 164 (bank-safe)
    __shared__ float vpp[8][3][16];      // per-warp Vp partials
    __shared__ float uws[81];            // U_w [27][3]
    const int t    = threadIdx.x;
    const int lane = t & 31, warp = t >> 5;
    const int w0 = blockIdx.x * 16;
    const int hh = blockIdx.y;
    const int bz = blockIdx.z;
    const int b  = bz >> 3, d = bz & 7;
    const float* Hb = g_h + b * (CCH * SPATIAL);

    if (t < 81) uws[t] = Uw[t];

    // --- load halo tile: 64 ch x 3 dz x 3 hy x 18 w (replicate-pad clamps) ---
    const int gw = min(max(w0 - 1 + lane, 0), 127);
#pragma unroll
    for (int r9 = 0; r9 < 9; ++r9) {
        const int dz = r9 / 3, hy = r9 % 3;
        const int gd = min(max(d  + dz - 1, 0), 7);
        const int gh = min(max(hh + hy - 1, 0), 127);
        const float* src = Hb + gd * HW2 + gh * 128 + gw;
        if (lane < 18) {
            for (int cc = warp; cc < 64; cc += 8)
                hs[cc * 164 + r9 * 18 + lane] = src[cc * SPATIAL];
        }
    }
    __syncthreads();

    const int pid = t & 15;     // position within w-tile
    const int cg  = t >> 4;     // channel group 0..15, channels cg*4..cg*4+3

    // --- Vp partials: this thread's 4 channels, then reduce ---
    float vw[4][3];
#pragma unroll
    for (int i = 0; i < 4; ++i)
#pragma unroll
        for (int r = 0; r < 3; ++r)
            vw[i][r] = __ldg(&Vw[(cg * 4 + i) * 3 + r]);

    float pv[3] = {0.f, 0.f, 0.f};
#pragma unroll
    for (int i = 0; i < 4; ++i) {
        float hv = hs[(cg * 4 + i) * 164 + 4 * 18 + 1 + pid];   // center tap
        pv[0] += hv * vw[i][0];
        pv[1] += hv * vw[i][1];
        pv[2] += hv * vw[i][2];
    }
#pragma unroll
    for (int r = 0; r < 3; ++r)
        pv[r] += __shfl_xor_sync(0xffffffffu, pv[r], 16);
    if (lane < 16) {
        vpp[warp][0][pid] = pv[0];
        vpp[warp][1][pid] = pv[1];
        vpp[warp][2][pid] = pv[2];
    }
    __syncthreads();

    // --- depthwise 3x3x3, 3 ranks, 4 channels per thread ---
    float up[4][3];
#pragma unroll
    for (int i = 0; i < 4; ++i) { up[i][0] = 0.f; up[i][1] = 0.f; up[i][2] = 0.f; }

#pragma unroll
    for (int r9 = 0; r9 < 9; ++r9) {
#pragma unroll
        for (int kx = 0; kx < 3; ++kx) {
            const float u0 = uws[(r9 * 3 + kx) * 3 + 0];
            const float u1 = uws[(r9 * 3 + kx) * 3 + 1];
            const float u2 = uws[(r9 * 3 + kx) * 3 + 2];
#pragma unroll
            for (int i = 0; i < 4; ++i) {
                float hv = hs[(cg * 4 + i) * 164 + r9 * 18 + kx + pid];
                up[i][0] += hv * u0;
                up[i][1] += hv * u1;
                up[i][2] += hv * u2;
            }
        }
    }

    // --- gather Vp across the 8 warps ---
    float vp0 = 0.f, vp1 = 0.f, vp2 = 0.f;
#pragma unroll
    for (int wv = 0; wv < 8; ++wv) {
        vp0 += vpp[wv][0][pid];
        vp1 += vpp[wv][1][pid];
        vp2 += vpp[wv][2][pid];
    }

    // --- normalize over ranks, contract with Vp, store UV ---
    float* UVb = g_uv + b * (CCH * SPATIAL) + d * HW2 + hh * 128 + w0 + pid;
#pragma unroll
    for (int i = 0; i < 4; ++i) {
        float s = up[i][0] * up[i][0] + up[i][1] * up[i][1] + up[i][2] * up[i][2];
        float inv = __fdividef(1.0f, 1e-6f + sqrtf(s));
        float uv = inv * (up[i][0] * vp0 + up[i][1] * vp1 + up[i][2] * vp2);
        UVb[(cg * 4 + i) * SPATIAL] = uv;
    }
}

// ---------------------------------------------------------------------------
extern "C" void kernel_launch(void* const* d_in, const int* in_sizes, int n_in,
                              void* d_out, int out_size) {
    const float* x      = (const float*)d_in[0];
    const float* head_w = (const float*)d_in[1];
    const float* tail_w = (const float*)d_in[2];
    const float* Uw     = (const float*)d_in[3];
    const float* Vw     = (const float*)d_in[4];
    float* out = (float*)d_out;

    dim3 gg(SPATIAL / 128, 2);
    gemm_head<<<gg, 256>>>(x, head_w);                    // h = head_w @ x
    midkernel<<<dim3(8, 128, 16), 256>>>(Uw, Vw);         // UV (fused middle)
    gemm_tail<<<gg, 256>>>(tail_w, out);                  // out = tail_w @ UV
}

// round 2
// speedup vs baseline: 1.3392x; 1.3392x over previous
#include <cuda_runtime.h>

#define SPATIAL 131072   // D*H*W per (batch, channel)
#define HW2     16384    // H*W

// Scratch (no allocations allowed anywhere)
__device__ float g_h [2 * 64 * SPATIAL];
__device__ float g_uv[2 * 64 * SPATIAL];
__device__ float g_vp[2 * 3  * SPATIAL];

typedef unsigned long long u64;

__device__ __forceinline__ u64 pack_dup(float x) {
    u64 u; asm("mov.b64 %0, {%1, %2};" : "=l"(u) : "f"(x), "f"(x)); return u;
}
__device__ __forceinline__ u64 pack2(float a, float b) {
    u64 u; asm("mov.b64 %0, {%1, %2};" : "=l"(u) : "f"(a), "f"(b)); return u;
}
__device__ __forceinline__ void fma2(u64& d, u64 a, u64 b) {
    asm("fma.rn.f32x2 %0, %1, %2, %0;" : "+l"(d) : "l"(a), "l"(b));
}
__device__ __forceinline__ float2 unpk(u64 v) {
    float2 f; asm("mov.b64 {%0, %1}, %2;" : "=f"(f.x), "=f"(f.y) : "l"(v)); return f;
}

// ---------------------------------------------------------------------------
// C[b][m][p] = sum_k A[m][k] * X[b][k][p]   (M=K=64, N=SPATIAL)
// CTA tile 64 x 256, thread tile 8m x 8n, packed f32x2 FMAs.
// VP_EPI: also compute Vp[b][r][p] = sum_m Vw[m][r] * C[m][p] (head only).
// ---------------------------------------------------------------------------
template<bool VP_EPI>
__device__ __forceinline__ void gemm64_body(const float* __restrict__ X,
                                            const float* __restrict__ A,
                                            float* __restrict__ C,
                                            const float* __restrict__ Vw) {
    extern __shared__ float Bs[];            // 64 * 256 floats = 64 KB
    __shared__ float As[64 * 64];            // As[k*64 + m] = A[m][k]
    const int t  = threadIdx.x;
    const int b  = blockIdx.y;
    const int p0 = blockIdx.x * 256;
    const float* Xb = X + b * (64 * SPATIAL);

#pragma unroll
    for (int i = 0; i < 4; ++i) {            // A transposed
        int fl = t + 256 * i;                // 1024 float4s
        int m = fl >> 4, kq = fl & 15;
        float4 v = *reinterpret_cast<const float4*>(A + m * 64 + kq * 4);
        As[(kq * 4 + 0) * 64 + m] = v.x;
        As[(kq * 4 + 1) * 64 + m] = v.y;
        As[(kq * 4 + 2) * 64 + m] = v.z;
        As[(kq * 4 + 3) * 64 + m] = v.w;
    }
#pragma unroll
    for (int i = 0; i < 16; ++i) {           // B tile 64 x 256
        int fl = t + 256 * i;                // 4096 float4s
        int k = fl >> 6, cq = fl & 63;
        *reinterpret_cast<float4*>(Bs + k * 256 + cq * 4) =
            *reinterpret_cast<const float4*>(Xb + k * SPATIAL + p0 + cq * 4);
    }
    __syncthreads();

    const int cg = t & 31;      // cols cg*8 .. cg*8+7
    const int rg = t >> 5;      // rows rg*8 .. rg*8+7
    u64 acc[32];
#pragma unroll
    for (int i = 0; i < 32; ++i) acc[i] = 0ull;

#pragma unroll 4
    for (int k = 0; k < 64; ++k) {
        float4 a0 = *reinterpret_cast<const float4*>(As + k * 64 + rg * 8);
        float4 a1 = *reinterpret_cast<const float4*>(As + k * 64 + rg * 8 + 4);
        float4 b0 = *reinterpret_cast<const float4*>(Bs + k * 256 + cg * 8);
        float4 b1 = *reinterpret_cast<const float4*>(Bs + k * 256 + cg * 8 + 4);
        u64 bp0 = pack2(b0.x, b0.y), bp1 = pack2(b0.z, b0.w);
        u64 bp2 = pack2(b1.x, b1.y), bp3 = pack2(b1.z, b1.w);
        float am[8] = {a0.x, a0.y, a0.z, a0.w, a1.x, a1.y, a1.z, a1.w};
#pragma unroll
        for (int j = 0; j < 8; ++j) {
            u64 aj = pack_dup(am[j]);
            fma2(acc[j * 4 + 0], aj, bp0);
            fma2(acc[j * 4 + 1], aj, bp1);
            fma2(acc[j * 4 + 2], aj, bp2);
            fma2(acc[j * 4 + 3], aj, bp3);
        }
    }

    float* Cb = C + b * (64 * SPATIAL);
#pragma unroll
    for (int j = 0; j < 8; ++j) {
        float2 q0 = unpk(acc[j * 4 + 0]), q1 = unpk(acc[j * 4 + 1]);
        float2 q2 = unpk(acc[j * 4 + 2]), q3 = unpk(acc[j * 4 + 3]);
        float* dst = Cb + (rg * 8 + j) * SPATIAL + p0 + cg * 8;
        *reinterpret_cast<float4*>(dst)     = make_float4(q0.x, q0.y, q1.x, q1.y);
        *reinterpret_cast<float4*>(dst + 4) = make_float4(q2.x, q2.y, q3.x, q3.y);
    }

    if (VP_EPI) {
        // Vp partials over this thread's 8 m-rows, packed pairs over its 8 cols
        u64 pvp[3][4];
#pragma unroll
        for (int r = 0; r < 3; ++r)
#pragma unroll
            for (int q = 0; q < 4; ++q) pvp[r][q] = 0ull;
#pragma unroll
        for (int j = 0; j < 8; ++j) {
            int m = rg * 8 + j;
#pragma unroll
            for (int r = 0; r < 3; ++r) {
                u64 vw = pack_dup(__ldg(&Vw[m * 3 + r]));
                fma2(pvp[r][0], vw, acc[j * 4 + 0]);
                fma2(pvp[r][1], vw, acc[j * 4 + 1]);
                fma2(pvp[r][2], vw, acc[j * 4 + 2]);
                fma2(pvp[r][3], vw, acc[j * 4 + 3]);
            }
        }
        __syncthreads();                      // Bs reads done -> reuse as vred
        float* vred = Bs;                     // [rowg 8][r 3][col 256]
#pragma unroll
        for (int r = 0; r < 3; ++r)
#pragma unroll
            for (int q = 0; q < 4; ++q)
                *reinterpret_cast<float2*>(vred + (rg * 3 + r) * 256 + cg * 8 + q * 2)
                    = unpk(pvp[r][q]);
        __syncthreads();
#pragma unroll
        for (int i = 0; i < 3; ++i) {
            int idx = t + 256 * i;            // 768 outputs
            int r = idx >> 8, col = idx & 255;
            float s = 0.f;
#pragma unroll
            for (int g = 0; g < 8; ++g) s += vred[(g * 3 + r) * 256 + col];
            g_vp[(b * 3 + r) * SPATIAL + p0 + col] = s;
        }
    }
}

__global__ void __launch_bounds__(256) gemm_head(const float* __restrict__ X,
                                                 const float* __restrict__ A,
                                                 const float* __restrict__ Vw) {
    gemm64_body<true>(X, A, g_h, Vw);
}
__global__ void __launch_bounds__(256) gemm_tail(const float* __restrict__ A,
                                                 float* __restrict__ C) {
    gemm64_body<false>(g_uv, A, C, nullptr);
}

// ---------------------------------------------------------------------------
// Fused middle: replicate-pad + depthwise 3x3x3 (3 ranks) + L2 norm over
// ranks + UV contraction with precomputed Vp.
// CTA = 8 channels x 4 h-rows x 128 w at fixed (b, d). 512 threads.
// Per-dz smem plane with register prefetch; packed f32x2 over w-pairs.
// ---------------------------------------------------------------------------
__global__ void __launch_bounds__(512) midkernel(const float* __restrict__ Uw) {
    __shared__ float tile[8 * 6 * 130];   // [c][hy][j] j = w+1 (halo)
    __shared__ float vpt[3 * 4 * 128];    // [r][hh][w]
    __shared__ u64   uwdup[81];           // U_w duplicated pairs
    const int t  = threadIdx.x;
    const int h0 = blockIdx.x * 4;
    const int c0 = blockIdx.y * 8;
    const int bz = blockIdx.z;
    const int b = bz >> 3, d = bz & 7;
    const float* Hb = g_h + (b * 64 + c0) * SPATIAL;

    if (t < 81) uwdup[t] = pack_dup(Uw[t]);

    // Vp tile load (no halo)
    {
        float vpr[3];
#pragma unroll
        for (int i = 0; i < 3; ++i) {
            int idx = t + 512 * i;            // idx = r*512 + hh*128 + w
            int r = idx >> 9, rem = idx & 511;
            vpr[i] = g_vp[(b * 3 + r) * SPATIAL + d * HW2 + h0 * 128 + rem];
        }
#pragma unroll
        for (int i = 0; i < 3; ++i) vpt[t + 512 * i] = vpr[i];
    }

    const int wp = t >> 5, lane = t & 31;
    float pf[3][5];

    // stage-dz halo plane loader: 48 rows (8c x 6hy) x 130 floats
#define LOADST(DZ)                                                          \
    {                                                                       \
        int gd = min(max(d + (DZ) - 1, 0), 7);                              \
        _Pragma("unroll")                                                   \
        for (int rr = 0; rr < 3; ++rr) {                                    \
            int row = wp + rr * 16;                                         \
            int c = row / 6, hy = row - c * 6;                              \
            int gh = min(max(h0 + hy - 1, 0), 127);                         \
            const float* src = Hb + c * SPATIAL + gd * HW2 + gh * 128;      \
            _Pragma("unroll")                                               \
            for (int q = 0; q < 5; ++q) {                                   \
                int j = lane + q * 32;                                      \
                pf[rr][q] = (j < 130) ? src[min(max(j - 1, 0), 127)] : 0.f; \
            }                                                               \
        }                                                                   \
    }
#define STOREST()                                                           \
    {                                                                       \
        _Pragma("unroll")                                                   \
        for (int rr = 0; rr < 3; ++rr) {                                    \
            int row = wp + rr * 16;                                         \
            _Pragma("unroll")                                               \
            for (int q = 0; q < 5; ++q) {                                   \
                int j = lane + q * 32;                                      \
                if (j < 130) tile[row * 130 + j] = pf[rr][q];               \
            }                                                               \
        }                                                                   \
    }

    const int c  = t >> 6;            // 0..7
    const int wl = t & 63;
    const int w  = wl * 2;            // output pair (w, w+1)
    u64 acc[4][3];
#pragma unroll
    for (int hh = 0; hh < 4; ++hh)
#pragma unroll
        for (int r = 0; r < 3; ++r) acc[hh][r] = 0ull;

    LOADST(0); STOREST(); __syncthreads();

#pragma unroll
    for (int dz = 0; dz < 3; ++dz) {
        if (dz < 2) LOADST(dz + 1);           // prefetch next plane into regs

        u64 wd[27];
#pragma unroll
        for (int j = 0; j < 27; ++j) wd[j] = uwdup[dz * 27 + j];

#pragma unroll
        for (int hy = 0; hy < 6; ++hy) {
            const float* rowp = &tile[c * 780 + hy * 130 + w];
            u64 v01 = *reinterpret_cast<const u64*>(rowp);
            u64 v23 = *reinterpret_cast<const u64*>(rowp + 2);
            float2 f01 = unpk(v01), f23 = unpk(v23);
            u64 v12 = pack2(f01.y, f23.x);
            u64 pr[3] = {v01, v12, v23};
            const int hh_lo = (hy >= 2) ? hy - 2 : 0;
            const int hh_hi = (hy < 3) ? hy : 3;
#pragma unroll
            for (int hh = 0; hh < 4; ++hh) {
                if (hh < hh_lo || hh > hh_hi) continue;
                const int hk = hy - hh;       // kernel h index 0..2
#pragma unroll
                for (int kx = 0; kx < 3; ++kx)
#pragma unroll
                    for (int r = 0; r < 3; ++r)
                        fma2(acc[hh][r], pr[kx], wd[(hk * 3 + kx) * 3 + r]);
            }
        }
        __syncthreads();
        if (dz < 2) { STOREST(); __syncthreads(); }
    }

    // normalize over ranks, contract with Vp, store UV (channels-major)
    float* UVb = g_uv + (b * 64 + c0 + c) * SPATIAL + d * HW2;
#pragma unroll
    for (int hh = 0; hh < 4; ++hh) {
        float2 u0 = unpk(acc[hh][0]), u1 = unpk(acc[hh][1]), u2 = unpk(acc[hh][2]);
        float2 vp0 = *reinterpret_cast<const float2*>(&vpt[0 * 512 + hh * 128 + w]);
        float2 vp1 = *reinterpret_cast<const float2*>(&vpt[1 * 512 + hh * 128 + w]);
        float2 vp2 = *reinterpret_cast<const float2*>(&vpt[2 * 512 + hh * 128 + w]);
        float sa = u0.x * u0.x + u1.x * u1.x + u2.x * u2.x;
        float sb = u0.y * u0.y + u1.y * u1.y + u2.y * u2.y;
        float ia = __fdividef(1.0f, 1e-6f + sqrtf(sa));
        float ib = __fdividef(1.0f, 1e-6f + sqrtf(sb));
        float oa = ia * (u0.x * vp0.x + u1.x * vp1.x + u2.x * vp2.x);
        float ob = ib * (u0.y * vp0.y + u1.y * vp1.y + u2.y * vp2.y);
        *reinterpret_cast<float2*>(UVb + (h0 + hh) * 128 + w) = make_float2(oa, ob);
    }
#undef LOADST
#undef STOREST
}

// ---------------------------------------------------------------------------
extern "C" void kernel_launch(void* const* d_in, const int* in_sizes, int n_in,
                              void* d_out, int out_size) {
    const float* x      = (const float*)d_in[0];
    const float* head_w = (const float*)d_in[1];
    const float* tail_w = (const float*)d_in[2];
    const float* Uw     = (const float*)d_in[3];
    const float* Vw     = (const float*)d_in[4];
    float* out = (float*)d_out;

    cudaFuncSetAttribute(gemm_head, cudaFuncAttributeMaxDynamicSharedMemorySize, 65536);
    cudaFuncSetAttribute(gemm_tail, cudaFuncAttributeMaxDynamicSharedMemorySize, 65536);

    dim3 gg(SPATIAL / 256, 2);
    gemm_head<<<gg, 256, 65536>>>(x, head_w, Vw);       // h = head_w @ x  (+ Vp)
    midkernel<<<dim3(32, 8, 16), 512>>>(Uw);            // UV (fused middle)
    gemm_tail<<<gg, 256, 65536>>>(tail_w, out);         // out = tail_w @ UV
}